// round 14
// baseline (speedup 1.0000x reference)
#include <cuda_runtime.h>
#include <cuda_bf16.h>
#include <cstdint>

// Batched complex QR (Q only), LAPACK Householder convention.
//   Input : x [B, 64, 16, 2] float32   Output: q [B, 64, 16, 2] float32
//
// ONE matrix per 32-lane warp. lane = (cg = lane>>3, rl = lane&7):
//   owns rows {rl+8t} x interleaved cols {cg+4u}.
// Reflector in UNNORMALIZED form (identical to clarfg):
//   u = x - beta*e_j,  H a = a - c*u*(u^H a),  c = conj(tau)/|alpha-beta|^2
//   u^H a_k = m_k - beta*a_jk,  m_k = full-column dot (pivot included)
// R diagonal slot stores 1/beta (only consumer is the Q division).
// Phase 2 uses separated re/im planes: zero swaps in the inner loop.
// This round: occupancy 4 -> 5 blocks/SM (102-reg target), body unchanged.

typedef unsigned long long u64;
#define NR    16
#define WPB   4                        // warps (= matrices) per block
#define ROWF2 17                       // padded row stride in float2
#define SXPM  (64 * ROWF2)
#define SRPM  136
#define SMEM_BYTES (WPB * (SXPM + SRPM) * (int)sizeof(float2))   // 39168
#define FULLM 0xffffffffu

__device__ __forceinline__ u64 PK(float lo, float hi) {
    u64 r; asm("mov.b64 %0,{%1,%2};" : "=l"(r) : "f"(lo), "f"(hi)); return r;
}
__device__ __forceinline__ void UPK(u64 v, float& lo, float& hi) {
    asm("mov.b64 {%0,%1},%2;" : "=f"(lo), "=f"(hi) : "l"(v));
}
__device__ __forceinline__ u64 DUP(float x) { return PK(x, x); }
__device__ __forceinline__ u64 SW(u64 z) {
    float a, b; UPK(z, a, b); return PK(b, a);
}
__device__ __forceinline__ u64 FMA2(u64 a, u64 b, u64 c) {
    u64 d; asm("fma.rn.f32x2 %0,%1,%2,%3;" : "=l"(d) : "l"(a), "l"(b), "l"(c)); return d;
}
__device__ __forceinline__ u64 MUL2(u64 a, u64 b) {
    u64 d; asm("mul.rn.f32x2 %0,%1,%2;" : "=l"(d) : "l"(a), "l"(b)); return d;
}
__device__ __forceinline__ u64 ADD2(u64 a, u64 b) {
    u64 d; asm("add.rn.f32x2 %0,%1,%2;" : "=l"(d) : "l"(a), "l"(b)); return d;
}
__device__ __forceinline__ u64 SHX2(u64 v, int s) {
    float a, b; UPK(v, a, b);
    a = __shfl_xor_sync(FULLM, a, s);
    b = __shfl_xor_sync(FULLM, b, s);
    return PK(a, b);
}
__device__ __forceinline__ u64 SHI2(u64 v, int src) {
    float a, b; UPK(v, a, b);
    a = __shfl_sync(FULLM, a, src);
    b = __shfl_sync(FULLM, b, src);
    return PK(a, b);
}

__global__ void __launch_bounds__(128, 5)
qr_householder_kernel(const float* __restrict__ in,
                      float* __restrict__ out,
                      int B)
{
    extern __shared__ float2 smem[];
    const int tid  = threadIdx.x;
    const int warp = tid >> 5;
    const int lane = tid & 31;
    const int cg   = lane >> 3;     // column group: owns cols cg+4u
    const int rl   = lane & 7;      // row lane:     owns rows rl+8t
    const long long b = (long long)blockIdx.x * WPB + warp;
    if (b >= B) return;

    float2* sxm = smem + warp * (SXPM + SRPM);
    float2* sRm = sxm + SXPM;

    // ---- coalesced load -> padded SMEM ----
    {
        const float4* src = (const float4*)(in + b * 2048);
#pragma unroll
        for (int it = 0; it < 16; it++) {
            const int idx = it * 32 + lane;
            const float4 v = src[idx];
            const int row = idx >> 3, cp = idx & 7;
            sxm[row * ROWF2 + 2 * cp]     = make_float2(v.x, v.y);
            sxm[row * ROWF2 + 2 * cp + 1] = make_float2(v.z, v.w);
        }
    }
    __syncwarp();

    // ---- register fill: A[t][u] = (row rl+8t, col cg+4u), packed (re,im) ----
    u64 A[8][4];
#pragma unroll
    for (int t = 0; t < 8; t++)
#pragma unroll
        for (int u = 0; u < 4; u++) {
            const float2 c = sxm[(rl + 8 * t) * ROWF2 + (cg + 4 * u)];
            A[t][u] = PK(c.x, c.y);
        }

    // ================= Householder elimination (cgeqrf) =================
#pragma unroll
    for (int j = 0; j < NR; j++) {
        const int uj = j >> 2, cgj = j & 3, tj = j >> 3, rlj = j & 7;

        // broadcast column j across groups (lane gets x at ITS rows)
        u64 xb[8];
#pragma unroll
        for (int t = tj; t < 8; t++)
            xb[t] = SHI2(A[t][uj], (cgj << 3) | rl);

        // alpha = x[row j]
        float alr, ali;
        { u64 al = SHI2(xb[tj], rlj); UPK(al, alr, ali); }

        // zero the strictly-above-pivot rows in slot tj (pivot keeps alpha)
        if (rl < rlj) xb[tj] = 0ull;

        // FULL-column dots m[u] = sum_{i>=j} conj(x_i)*a_ik  and ss = ||x||^2
        float ss = 0.f;
        u64 P[4], Q[4];
#pragma unroll
        for (int u = 0; u < 4; u++)
            if (4 * u + 3 > j) { P[u] = 0ull; Q[u] = 0ull; }
#pragma unroll
        for (int t = tj; t < 8; t++) {
            float xr, xi; UPK(xb[t], xr, xi);
            ss = fmaf(xr, xr, fmaf(xi, xi, ss));
            const u64 XR = DUP(xr), XI = DUP(xi);
#pragma unroll
            for (int u = 0; u < 4; u++)
                if (4 * u + 3 > j) {
                    P[u] = FMA2(XR, A[t][u], P[u]);
                    Q[u] = FMA2(XI, A[t][u], Q[u]);
                }
        }
        // combine: m = (P.lo + Q.hi, P.hi - Q.lo)
        u64 m[4];
#pragma unroll
        for (int u = 0; u < 4; u++)
            if (4 * u + 3 > j) {
                float pr, pi, qr, qi;
                UPK(P[u], pr, pi); UPK(Q[u], qr, qi);
                m[u] = PK(pr + qi, pi - qr);
            }
        // 3-round butterfly within the 8-lane row group
#pragma unroll
        for (int s = 4; s; s >>= 1) {
            ss += __shfl_xor_sync(FULLM, ss, s);
#pragma unroll
            for (int u = 0; u < 4; u++)
                if (4 * u + 3 > j)
                    m[u] = ADD2(m[u], SHX2(m[u], s));
        }

        // scalars (exact LAPACK clarfg convention); ib = 1/beta kept for Q
        float bet, ib, ccr, cci, dr, di;
        const float chk = fmaf(alr, alr, ali * ali);
        if (ss == chk && ali == 0.f) {       // tail exactly zero -> tau = 0
            bet = alr; ib = __fdividef(1.f, alr);
            ccr = 0.f; cci = 0.f; dr = 0.f; di = 0.f;
        } else {
            const float rn  = rsqrtf(ss);
            const float sgn = (alr >= 0.f) ? 1.f : -1.f;
            bet = -sgn * (ss * rn);
            ib  = -sgn * rn;                          // 1/beta
            dr = alr - bet; di = ali;
            const float dd = __fdividef(1.f, fmaf(dr, dr, di * di));
            const float f  = ib * dd;
            ccr = (bet - alr) * f;                    // c = conj(tau)/|a-b|^2
            cci = ali * f;
        }
        const u64 CCR = DUP(ccr), CCS = PK(-cci, cci);
        const u64 NB  = DUP(-bet);

        // pivot entry of u is (alpha - beta)
        if (rl == rlj) xb[tj] = PK(dr, di);

        // per active column: uh = m - beta*ajk, g = c*uh
        u64 NG[4], GS[4];
#pragma unroll
        for (int u = 0; u < 4; u++)
            if (4 * u + 3 > j) {
                const u64 ajk = SHI2(A[tj][u], (cg << 3) | rlj);
                const u64 uh  = FMA2(NB, ajk, m[u]);
                const u64 g   = FMA2(CCR, uh, MUL2(CCS, SW(uh)));
                float gr, gi; UPK(g, gr, gi);
                NG[u] = DUP(-gr);
                GS[u] = PK(gi, -gi);    // -g*u = NG*u + GS*SW(u)
            }

        // rank-1 update: A -= g * u  (rows above pivot have u = 0)
#pragma unroll
        for (int t = tj; t < 8; t++) {
            const u64 v = xb[t], sv = SW(v);
#pragma unroll
            for (int u = 0; u < 4; u++)
                if (4 * u + 3 > j) {
                    if (4 * u > j || (cg + 4 * u > j))
                        A[t][u] = FMA2(NG[u], v, FMA2(GS[u], sv, A[t][u]));
                }
        }
        // R diagonal slot stores 1/beta (real)
        if (cg == cgj && rl == rlj) A[tj][uj] = PK(ib, 0.f);
    }

    // ---- publish R (packed upper triangle; diag slot = 1/beta) ----
#pragma unroll
    for (int u = 0; u < 4; u++) {
        const int col = cg + 4 * u;
#pragma unroll
        for (int t = 0; t < 2; t++) {      // rows 0..15 live in t=0,1
            const int i = rl + 8 * t;
            if (i <= col) {
                float rr, ri; UPK(A[t][u], rr, ri);
                sRm[(col * (col + 1)) / 2 + i] = make_float2(rr, ri);
            }
        }
    }
    __syncwarp();

    // ========== Q = X * R^{-1} back-substitution (rows lane, lane+32) ==========
    // Separated planes: qr[k] = (re_l, re_l32), qi[k] = (im_l, im_l32).
    u64 qr[NR], qi[NR];
#pragma unroll
    for (int k = 0; k < NR; k++) {
        const float2 y0 = sxm[lane * ROWF2 + k];
        const float2 y1 = sxm[(lane + 32) * ROWF2 + k];
        u64 yr = PK(y0.x, y1.x);
        u64 yi = PK(y0.y, y1.y);
#pragma unroll
        for (int i = 0; i < k; i++) {
            const float2 rc = sRm[(k * (k + 1)) / 2 + i];   // R[i][k]
            const u64 NRR = DUP(-rc.x), RID = DUP(rc.y), NRI = DUP(-rc.y);
            yr = FMA2(NRR, qr[i], FMA2(RID, qi[i], yr));
            yi = FMA2(NRR, qi[i], FMA2(NRI, qr[i], yi));
        }
        const u64 IB = DUP(sRm[(k * (k + 1)) / 2 + k].x);   // 1/beta_k
        qr[k] = MUL2(yr, IB);
        qi[k] = MUL2(yi, IB);
    }

    // ---- stage Q back into sx (this lane's own rows only) ----
#pragma unroll
    for (int k = 0; k < NR; k++) {
        float r0, r1, i0, i1;
        UPK(qr[k], r0, r1); UPK(qi[k], i0, i1);
        sxm[lane * ROWF2 + k]        = make_float2(r0, i0);
        sxm[(lane + 32) * ROWF2 + k] = make_float2(r1, i1);
    }
    __syncwarp();

    // ---- coalesced store ----
    {
        float4* dst = (float4*)(out + b * 2048);
#pragma unroll
        for (int it = 0; it < 16; it++) {
            const int idx = it * 32 + lane;
            const int row = idx >> 3, cp = idx & 7;
            const float2 v0 = sxm[row * ROWF2 + 2 * cp];
            const float2 v1 = sxm[row * ROWF2 + 2 * cp + 1];
            dst[idx] = make_float4(v0.x, v0.y, v1.x, v1.y);
        }
    }
}

extern "C" void kernel_launch(void* const* d_in, const int* in_sizes, int n_in,
                              void* d_out, int out_size)
{
    const float* x = (const float*)d_in[0];
    float* q = (float*)d_out;
    const int B = in_sizes[0] / (64 * NR * 2);   // 32768

    cudaFuncSetAttribute(qr_householder_kernel,
                         cudaFuncAttributeMaxDynamicSharedMemorySize,
                         SMEM_BYTES);

    const int grid = (B + WPB - 1) / WPB;
    qr_householder_kernel<<<grid, WPB * 32, SMEM_BYTES>>>(x, q, B);
}

// round 15
// speedup vs baseline: 1.1972x; 1.1972x over previous
#include <cuda_runtime.h>
#include <cuda_bf16.h>
#include <cstdint>

// Batched complex QR (Q only), LAPACK Householder convention.
//   Input : x [B, 64, 16, 2] float32   Output: q [B, 64, 16, 2] float32
//
// ONE matrix per 32-lane warp. lane = (cg = lane>>3, rl = lane&7):
//   owns rows {rl+8t} x interleaved cols {cg+4u}.
// Reflector in UNNORMALIZED form (identical to clarfg):
//   u = x - beta*e_j,  H a = a - c*u*(u^H a),  c = conj(tau)/|alpha-beta|^2
//   u^H a_k = m_k - beta*a_jk,  m_k = full-column dot (pivot included)
// R diagonal slot stores 1/beta. Phase 2 separated re/im planes (no swaps).
// NEW: software-pipelined column broadcast — next pivot column's shfl is
// issued per row-block immediately after that block's rank-1 update, so the
// 26-cyc shuffle latency hides under the remaining update FMAs.

typedef unsigned long long u64;
#define NR    16
#define WPB   4                        // warps (= matrices) per block
#define ROWF2 17                       // padded row stride in float2
#define SXPM  (64 * ROWF2)
#define SRPM  136
#define SMEM_BYTES (WPB * (SXPM + SRPM) * (int)sizeof(float2))   // 39168
#define FULLM 0xffffffffu

__device__ __forceinline__ u64 PK(float lo, float hi) {
    u64 r; asm("mov.b64 %0,{%1,%2};" : "=l"(r) : "f"(lo), "f"(hi)); return r;
}
__device__ __forceinline__ void UPK(u64 v, float& lo, float& hi) {
    asm("mov.b64 {%0,%1},%2;" : "=f"(lo), "=f"(hi) : "l"(v));
}
__device__ __forceinline__ u64 DUP(float x) { return PK(x, x); }
__device__ __forceinline__ u64 SW(u64 z) {
    float a, b; UPK(z, a, b); return PK(b, a);
}
__device__ __forceinline__ u64 FMA2(u64 a, u64 b, u64 c) {
    u64 d; asm("fma.rn.f32x2 %0,%1,%2,%3;" : "=l"(d) : "l"(a), "l"(b), "l"(c)); return d;
}
__device__ __forceinline__ u64 MUL2(u64 a, u64 b) {
    u64 d; asm("mul.rn.f32x2 %0,%1,%2;" : "=l"(d) : "l"(a), "l"(b)); return d;
}
__device__ __forceinline__ u64 ADD2(u64 a, u64 b) {
    u64 d; asm("add.rn.f32x2 %0,%1,%2;" : "=l"(d) : "l"(a), "l"(b)); return d;
}
__device__ __forceinline__ u64 SHX2(u64 v, int s) {
    float a, b; UPK(v, a, b);
    a = __shfl_xor_sync(FULLM, a, s);
    b = __shfl_xor_sync(FULLM, b, s);
    return PK(a, b);
}
__device__ __forceinline__ u64 SHI2(u64 v, int src) {
    float a, b; UPK(v, a, b);
    a = __shfl_sync(FULLM, a, src);
    b = __shfl_sync(FULLM, b, src);
    return PK(a, b);
}

__global__ void __launch_bounds__(128, 4)
qr_householder_kernel(const float* __restrict__ in,
                      float* __restrict__ out,
                      int B)
{
    extern __shared__ float2 smem[];
    const int tid  = threadIdx.x;
    const int warp = tid >> 5;
    const int lane = tid & 31;
    const int cg   = lane >> 3;     // column group: owns cols cg+4u
    const int rl   = lane & 7;      // row lane:     owns rows rl+8t
    const long long b = (long long)blockIdx.x * WPB + warp;
    if (b >= B) return;

    float2* sxm = smem + warp * (SXPM + SRPM);
    float2* sRm = sxm + SXPM;

    // ---- coalesced load -> padded SMEM ----
    {
        const float4* src = (const float4*)(in + b * 2048);
#pragma unroll
        for (int it = 0; it < 16; it++) {
            const int idx = it * 32 + lane;
            const float4 v = src[idx];
            const int row = idx >> 3, cp = idx & 7;
            sxm[row * ROWF2 + 2 * cp]     = make_float2(v.x, v.y);
            sxm[row * ROWF2 + 2 * cp + 1] = make_float2(v.z, v.w);
        }
    }
    __syncwarp();

    // ---- register fill: A[t][u] = (row rl+8t, col cg+4u), packed (re,im) ----
    u64 A[8][4];
#pragma unroll
    for (int t = 0; t < 8; t++)
#pragma unroll
        for (int u = 0; u < 4; u++) {
            const float2 c = sxm[(rl + 8 * t) * ROWF2 + (cg + 4 * u)];
            A[t][u] = PK(c.x, c.y);
        }

    // ---- prologue: broadcast column 0 (slot 0, group 0) ----
    u64 xb[8];
#pragma unroll
    for (int t = 0; t < 8; t++)
        xb[t] = SHI2(A[t][0], rl);          // src lane = (0<<3)|rl

    // ================= Householder elimination (cgeqrf) =================
#pragma unroll
    for (int j = 0; j < NR; j++) {
        const int uj = j >> 2, cgj = j & 3, tj = j >> 3, rlj = j & 7;
        (void)uj; (void)cgj;

        // alpha = x[row j] (xb already holds broadcast column j)
        float alr, ali;
        { u64 al = SHI2(xb[tj], rlj); UPK(al, alr, ali); }

        // zero the strictly-above-pivot rows in slot tj (pivot keeps alpha)
        if (rl < rlj) xb[tj] = 0ull;

        // FULL-column dots m[u] = sum_{i>=j} conj(x_i)*a_ik  and ss = ||x||^2
        float ss = 0.f;
        u64 P[4], Q[4];
#pragma unroll
        for (int u = 0; u < 4; u++)
            if (4 * u + 3 > j) { P[u] = 0ull; Q[u] = 0ull; }
#pragma unroll
        for (int t = tj; t < 8; t++) {
            float xr, xi; UPK(xb[t], xr, xi);
            ss = fmaf(xr, xr, fmaf(xi, xi, ss));
            const u64 XR = DUP(xr), XI = DUP(xi);
#pragma unroll
            for (int u = 0; u < 4; u++)
                if (4 * u + 3 > j) {
                    P[u] = FMA2(XR, A[t][u], P[u]);
                    Q[u] = FMA2(XI, A[t][u], Q[u]);
                }
        }
        // combine: m = (P.lo + Q.hi, P.hi - Q.lo)
        u64 m[4];
#pragma unroll
        for (int u = 0; u < 4; u++)
            if (4 * u + 3 > j) {
                float pr, pi, qr, qi;
                UPK(P[u], pr, pi); UPK(Q[u], qr, qi);
                m[u] = PK(pr + qi, pi - qr);
            }
        // 3-round butterfly within the 8-lane row group
#pragma unroll
        for (int s = 4; s; s >>= 1) {
            ss += __shfl_xor_sync(FULLM, ss, s);
#pragma unroll
            for (int u = 0; u < 4; u++)
                if (4 * u + 3 > j)
                    m[u] = ADD2(m[u], SHX2(m[u], s));
        }

        // scalars (exact LAPACK clarfg convention); ib = 1/beta kept for Q
        float bet, ib, ccr, cci, dr, di;
        const float chk = fmaf(alr, alr, ali * ali);
        if (ss == chk && ali == 0.f) {       // tail exactly zero -> tau = 0
            bet = alr; ib = __fdividef(1.f, alr);
            ccr = 0.f; cci = 0.f; dr = 0.f; di = 0.f;
        } else {
            const float rn  = rsqrtf(ss);
            const float sgn = (alr >= 0.f) ? 1.f : -1.f;
            bet = -sgn * (ss * rn);
            ib  = -sgn * rn;                          // 1/beta
            dr = alr - bet; di = ali;
            const float dd = __fdividef(1.f, fmaf(dr, dr, di * di));
            const float f  = ib * dd;
            ccr = (bet - alr) * f;                    // c = conj(tau)/|a-b|^2
            cci = ali * f;
        }
        const u64 CCR = DUP(ccr), CCS = PK(-cci, cci);
        const u64 NB  = DUP(-bet);

        // pivot entry of u is (alpha - beta)
        if (rl == rlj) xb[tj] = PK(dr, di);

        // per active column: uh = m - beta*ajk, g = c*uh
        u64 NG[4], GS[4];
#pragma unroll
        for (int u = 0; u < 4; u++)
            if (4 * u + 3 > j) {
                const u64 ajk = SHI2(A[tj][u], (cg << 3) | rlj);
                const u64 uh  = FMA2(NB, ajk, m[u]);
                const u64 g   = FMA2(CCR, uh, MUL2(CCS, SW(uh)));
                float gr, gi; UPK(g, gr, gi);
                NG[u] = DUP(-gr);
                GS[u] = PK(gi, -gi);    // -g*u = NG*u + GS*SW(u)
            }

        // next-step broadcast parameters
        const int ujn   = (j + 1) >> 2;
        const int srcvn = (((j + 1) & 3) << 3) | rl;

        // rank-1 update per row-block t, then IMMEDIATELY issue the next
        // pivot column's broadcast for that t (pipelines shfl under FMAs).
#pragma unroll
        for (int t = tj; t < 8; t++) {
            const u64 v = xb[t], sv = SW(v);
#pragma unroll
            for (int u = 0; u < 4; u++)
                if (4 * u + 3 > j) {
                    if (4 * u > j || (cg + 4 * u > j))
                        A[t][u] = FMA2(NG[u], v, FMA2(GS[u], sv, A[t][u]));
                }
            if (j < NR - 1)
                xb[t] = SHI2(A[t][ujn], srcvn);
        }
        // R diagonal slot stores 1/beta (real)
        if (cg == cgj && rl == rlj) A[tj][uj] = PK(ib, 0.f);
    }

    // ---- publish R (packed upper triangle; diag slot = 1/beta) ----
#pragma unroll
    for (int u = 0; u < 4; u++) {
        const int col = cg + 4 * u;
#pragma unroll
        for (int t = 0; t < 2; t++) {      // rows 0..15 live in t=0,1
            const int i = rl + 8 * t;
            if (i <= col) {
                float rr, ri; UPK(A[t][u], rr, ri);
                sRm[(col * (col + 1)) / 2 + i] = make_float2(rr, ri);
            }
        }
    }
    __syncwarp();

    // ========== Q = X * R^{-1} back-substitution (rows lane, lane+32) ==========
    // Separated planes: qr[k] = (re_l, re_l32), qi[k] = (im_l, im_l32).
    u64 qr[NR], qi[NR];
#pragma unroll
    for (int k = 0; k < NR; k++) {
        const float2 y0 = sxm[lane * ROWF2 + k];
        const float2 y1 = sxm[(lane + 32) * ROWF2 + k];
        u64 yr = PK(y0.x, y1.x);
        u64 yi = PK(y0.y, y1.y);
#pragma unroll
        for (int i = 0; i < k; i++) {
            const float2 rc = sRm[(k * (k + 1)) / 2 + i];   // R[i][k]
            const u64 NRR = DUP(-rc.x), RID = DUP(rc.y), NRI = DUP(-rc.y);
            yr = FMA2(NRR, qr[i], FMA2(RID, qi[i], yr));
            yi = FMA2(NRR, qi[i], FMA2(NRI, qr[i], yi));
        }
        const u64 IB = DUP(sRm[(k * (k + 1)) / 2 + k].x);   // 1/beta_k
        qr[k] = MUL2(yr, IB);
        qi[k] = MUL2(yi, IB);
    }

    // ---- stage Q back into sx (this lane's own rows only) ----
#pragma unroll
    for (int k = 0; k < NR; k++) {
        float r0, r1, i0, i1;
        UPK(qr[k], r0, r1); UPK(qi[k], i0, i1);
        sxm[lane * ROWF2 + k]        = make_float2(r0, i0);
        sxm[(lane + 32) * ROWF2 + k] = make_float2(r1, i1);
    }
    __syncwarp();

    // ---- coalesced store ----
    {
        float4* dst = (float4*)(out + b * 2048);
#pragma unroll
        for (int it = 0; it < 16; it++) {
            const int idx = it * 32 + lane;
            const int row = idx >> 3, cp = idx & 7;
            const float2 v0 = sxm[row * ROWF2 + 2 * cp];
            const float2 v1 = sxm[row * ROWF2 + 2 * cp + 1];
            dst[idx] = make_float4(v0.x, v0.y, v1.x, v1.y);
        }
    }
}

extern "C" void kernel_launch(void* const* d_in, const int* in_sizes, int n_in,
                              void* d_out, int out_size)
{
    const float* x = (const float*)d_in[0];
    float* q = (float*)d_out;
    const int B = in_sizes[0] / (64 * NR * 2);   // 32768

    cudaFuncSetAttribute(qr_householder_kernel,
                         cudaFuncAttributeMaxDynamicSharedMemorySize,
                         SMEM_BYTES);

    const int grid = (B + WPB - 1) / WPB;
    qr_householder_kernel<<<grid, WPB * 32, SMEM_BYTES>>>(x, q, B);
}